// round 15
// baseline (speedup 1.0000x reference)
#include <cuda_runtime.h>
#include <cuda_bf16.h>
#include <math.h>

// Problem constants (fixed by reference setup_inputs)
#define BB 8
#define TT 16
#define CC 64
#define NN 4096          // H*W
#define KSEL 2048        // keep_k = N*(1-0.5)

#define CHUNKB 4         // batches per K1/S chunk
#define MHALFB 2         // batches per M launch (write window control)
#define FULL 0xffffffffu

// Scratch (device globals — no allocation allowed)
__device__ float g_sq[BB * TT * NN];             // sqrt(sum_c x^2) per (b,t,n), 2 MB
__device__ unsigned g_maskbits[BB * (NN / 32)];  // 1 bit per (b,n)

// ---------------------------------------------------------------------------
// K1 (R1-proven form, chunked): partial = sqrt(sum_c x[b,t,c,n]^2).
// 262144 threads per chunk, 64 coalesced loads each (stride NN), no smem.
// Bit-exact same accumulation order as the verified R1 kernel.
// ---------------------------------------------------------------------------
__global__ void __launch_bounds__(256) k1_score(const float* __restrict__ x,
                                                int chunk) {
    const int idx = blockIdx.x * 256 + threadIdx.x;   // [0, CHUNKB*TT*NN)
    const int n   = idx & (NN - 1);
    const int btl = idx >> 12;                        // 0..63
    const int bt  = chunk * (CHUNKB * TT) + btl;

    const float* p = x + (size_t)bt * CC * NN + n;
    float acc = 0.0f;
#pragma unroll
    for (int c = 0; c < CC; ++c) {
        float v = p[(size_t)c * NN];
        acc += v * v;
    }
    g_sq[(size_t)bt * NN + n] = sqrtf(acc);
}

// ---------------------------------------------------------------------------
// S (R14-verified): per-batch exact top-K -> mask bits via histogram
// radix-256. Exact threshold + lowest-index tie tail.
// ---------------------------------------------------------------------------
__global__ void __launch_bounds__(1024, 1) k_select(int chunk) {
    __shared__ int s_hist[256];
    __shared__ int s_suf[256];
    __shared__ int s_wtot[8];
    __shared__ unsigned s_or[32], s_and[32];
    __shared__ unsigned s_mask[NN / 32];
    __shared__ int s_scan[32];

    const int b    = chunk * CHUNKB + blockIdx.x;
    const int j    = threadIdx.x;              // 0..1023
    const int lane = j & 31;
    const int wid  = j >> 5;

    // --- scores: 4 per thread, sequential over t (verified order) ---
    const float4* part = (const float4*)g_sq;
    float s0 = 0.f, s1 = 0.f, s2 = 0.f, s3 = 0.f;
#pragma unroll
    for (int t = 0; t < TT; ++t) {
        float4 f = part[(size_t)(b * TT + t) * (NN / 4) + j];
        s0 += f.x; s1 += f.y; s2 += f.z; s3 += f.w;
    }
    const float inv = 1.0f / (float)TT;
    unsigned u0 = __float_as_uint(s0 * inv);
    unsigned u1 = __float_as_uint(s1 * inv);
    unsigned u2 = __float_as_uint(s2 * inv);
    unsigned u3 = __float_as_uint(s3 * inv);

    if (j < NN / 32) s_mask[j] = 0u;

    // --- block OR / AND: common-prefix detection ---
    {
        unsigned ow = __reduce_or_sync(FULL, u0 | u1 | u2 | u3);
        unsigned aw = __reduce_and_sync(FULL, u0 & u1 & u2 & u3);
        if (lane == 0) { s_or[wid] = ow; s_and[wid] = aw; }
    }
    __syncthreads();
    const unsigned orv  = __reduce_or_sync(FULL, s_or[lane]);
    const unsigned andv = __reduce_and_sync(FULL, s_and[lane]);
    const unsigned diff = orv ^ andv;

    // --- histogram radix-256 select ---
    const int hb = diff ? (31 - __clz((int)diff)) : 0;
    int shift = (hb >= 7) ? (hb - 7) : 0;      // round 1 covers hb..hb-7
    int det   = shift + 8;                      // lowest determined bit
    unsigned hi = (det < 32) ? (andv & ~((1u << det) - 1u)) : 0u;
    int G = 0;                                  // count(u > current prefix)

    for (;;) {
        if (j < 256) s_hist[j] = 0;
        __syncthreads();

        if (det >= 32 || ((u0 ^ hi) >> det) == 0u)
            atomicAdd(&s_hist[(u0 >> shift) & 0xFF], 1);
        if (det >= 32 || ((u1 ^ hi) >> det) == 0u)
            atomicAdd(&s_hist[(u1 >> shift) & 0xFF], 1);
        if (det >= 32 || ((u2 ^ hi) >> det) == 0u)
            atomicAdd(&s_hist[(u2 >> shift) & 0xFF], 1);
        if (det >= 32 || ((u3 ^ hi) >> det) == 0u)
            atomicAdd(&s_hist[(u3 >> shift) & 0xFF], 1);
        __syncthreads();

        // suffix sums over 256 bins
        int h = (j < 256) ? s_hist[j] : 0;
        int v = h;
#pragma unroll
        for (int d2 = 1; d2 < 32; d2 <<= 1) {
            int t = __shfl_down_sync(FULL, v, d2);
            if (lane + d2 < 32) v += t;
        }
        if (j < 256 && lane == 0) s_wtot[wid] = v;
        __syncthreads();
        int fj = 0;
        if (j < 256) {
            int carry = 0;
#pragma unroll
            for (int w2 = 1; w2 < 8; ++w2)
                if (w2 > wid) carry += s_wtot[w2];
            int Sj = v + carry;
            s_suf[j] = Sj;
            fj = (G + Sj >= KSEL) ? 1 : 0;
        }
        int cnt = __syncthreads_count(fj);
        int d = cnt - 1;                        // largest feasible digit
        G += (d < 255) ? s_suf[d + 1] : 0;
        hi |= ((unsigned)d) << shift;
        det = shift;
        if (shift == 0) break;
        shift = (shift >= 8) ? (shift - 8) : 0;
        __syncthreads();
    }

    const unsigned thr = hi;
    const int need = KSEL - G;

    // --- exclusive scan of equal-counts (lowest-index tie admit) ---
    int e = (u0 == thr) + (u1 == thr) + (u2 == thr) + (u3 == thr);
    int v2 = e;
#pragma unroll
    for (int d = 1; d < 32; d <<= 1) {
        int t = __shfl_up_sync(FULL, v2, d);
        if (lane >= d) v2 += t;
    }
    if (lane == 31) s_scan[wid] = v2;
    __syncthreads();
    if (wid == 0) {
        int w = s_scan[lane];
#pragma unroll
        for (int d = 1; d < 32; d <<= 1) {
            int t = __shfl_up_sync(FULL, w, d);
            if (lane >= d) w += t;
        }
        s_scan[lane] = w;
    }
    __syncthreads();
    int excl = v2 - e + (wid ? s_scan[wid - 1] : 0);

    unsigned nib = 0;
    int r = excl;
    unsigned uu[4] = {u0, u1, u2, u3};
#pragma unroll
    for (int i = 0; i < 4; ++i) {
        if (uu[i] > thr) {
            nib |= 1u << i;
        } else if (uu[i] == thr) {
            if (r < need) nib |= 1u << i;
            ++r;
        }
    }
    atomicOr(&s_mask[j >> 3], nib << ((j & 7) * 4));
    __syncthreads();
    if (j < NN / 32) g_maskbits[b * (NN / 32) + j] = s_mask[j];
}

// ---------------------------------------------------------------------------
// M: masked copy for a 2-batch half (write-window control: x(chunk) 67MB +
// out-half 33.5MB fits L2, so every __ldcs read is an L2 hit).
// ---------------------------------------------------------------------------
__global__ void __launch_bounds__(256) k_mask(const float4* __restrict__ x4,
                                              float4* __restrict__ o4,
                                              int mhalf) {
    unsigned i = (unsigned)mhalf * (MHALFB * TT * CC * (NN / 4))
               + blockIdx.x * 256 + threadIdx.x;
    int n4 = i & ((NN / 4) - 1);
    int b  = i >> 20;                        // 2^20 float4 per batch
    int n  = n4 << 2;
    unsigned mword = g_maskbits[(b << 7) + (n >> 5)];
    unsigned bits  = mword >> (n & 31);
    float4 v = __ldcs(&x4[(size_t)i]);
    v.x = (bits & 1u) ? v.x : 0.0f;
    v.y = (bits & 2u) ? v.y : 0.0f;
    v.z = (bits & 4u) ? v.z : 0.0f;
    v.w = (bits & 8u) ? v.w : 0.0f;
    __stcs(&o4[(size_t)i], v);
}

// ---------------------------------------------------------------------------
extern "C" void kernel_launch(void* const* d_in, const int* in_sizes, int n_in,
                              void* d_out, int out_size) {
    const float* x = (const float*)d_in[0];
    float* out = (float*)d_out;

    const int K1_GRID = CHUNKB * TT * NN / 256;              // 1024 blocks
    const int M_GRID  = MHALFB * TT * CC * NN / 4 / 256;     // 8192 blocks

    // Per chunk: K1 streams x(chunk) through L2, S picks masks, two M halves
    // re-read x from L2 and stream out (each half's write set fits alongside).
    k1_score<<<K1_GRID, 256>>>(x, 0);
    k_select<<<CHUNKB, 1024>>>(0);
    k_mask<<<M_GRID, 256>>>((const float4*)x, (float4*)out, 0);
    k_mask<<<M_GRID, 256>>>((const float4*)x, (float4*)out, 1);
    k1_score<<<K1_GRID, 256>>>(x, 1);
    k_select<<<CHUNKB, 1024>>>(1);
    k_mask<<<M_GRID, 256>>>((const float4*)x, (float4*)out, 2);
    k_mask<<<M_GRID, 256>>>((const float4*)x, (float4*)out, 3);
}